// round 16
// baseline (speedup 1.0000x reference)
#include <cuda_runtime.h>
#include <cuda_bf16.h>
#include <cuda_fp16.h>
#include <math.h>

// Problem constants
#define BB   4
#define LL   2048
#define DD   1024
#define KK   16
#define BL   (BB*LL)        // 8192 tokens
#define NCH  128            // scan chunks (occupancy)
#define LC   (LL/NCH)       // 16 tokens per chunk

// ---------------------------------------------------------------------------
// Scratch (no allocation allowed -> __device__ globals)
// ---------------------------------------------------------------------------
__device__ __half g_valh[BL*DD];            // 16 MB (value, fp16)
__device__ __half g_reth[BL*DD];            // 16 MB (retrieved, fp16, pre-LN)
__device__ float g_ck   [BL*KK];
__device__ float g_cq   [BL*KK];
__device__ __half g_Sh  [BB*NCH*KK*DD];     // 16 MB chunk states (fp16)

// fp16 operand panels, chunk-major, swizzled (cell ^ (row&7)) layout.
__device__ uint4 g_ahi[(16*8192*128)/16];   // 16 MB (x, later normed)
__device__ uint4 g_bhi[(16*1024*128)/16];   // 2 MB  (Wv)
__device__ uint4 g_bhi2[(16*1024*128)/16];  // 2 MB  (Wo)

// ---------------------------------------------------------------------------
// PTX helpers (base sm_90/sm_80 features only — target is plain sm_100!)
// ---------------------------------------------------------------------------
__device__ __forceinline__ unsigned smem_u32(const void* p) {
    unsigned a;
    asm("{ .reg .u64 t; cvta.to.shared.u64 t, %1; cvt.u32.u64 %0, t; }" : "=r"(a) : "l"(p));
    return a;
}

#define MBAR_INIT(addr, cnt) \
    asm volatile("mbarrier.init.shared.b64 [%0], %1;" :: "r"(addr), "r"(cnt) : "memory")
#define MBAR_INVAL(addr) \
    asm volatile("mbarrier.inval.shared.b64 [%0];" :: "r"(addr) : "memory")
#define MBAR_EXPECT_TX(addr, bytes) \
    asm volatile("mbarrier.arrive.expect_tx.shared.b64 _, [%0], %1;" :: "r"(addr), "r"(bytes) : "memory")
#define MBAR_ARRIVE(addr) \
    asm volatile("mbarrier.arrive.shared.b64 _, [%0];" :: "r"(addr) : "memory")

#define MBAR_WAIT(addr, par) do {                                              \
    unsigned _m = (addr), _p = (par), _d;                                      \
    asm volatile("{\n\t.reg .pred p;\n\t"                                      \
        "mbarrier.try_wait.parity.acquire.cta.shared::cta.b64 p, [%1], %2;\n\t"\
        "selp.b32 %0, 1, 0, p;\n\t}"                                           \
        : "=r"(_d) : "r"(_m), "r"(_p) : "memory");                             \
    if (!_d) {                                                                 \
        asm volatile("{\n\t.reg .pred P1;\n\t"                                 \
            "W%=:\n\t"                                                         \
            "mbarrier.try_wait.parity.acquire.cta.shared::cta.b64 P1, [%0], %1, 0x989680;\n\t" \
            "@P1 bra.uni D%=;\n\t"                                             \
            "bra.uni W%=;\n\t"                                                 \
            "D%=:\n\t}" :: "r"(_m), "r"(_p) : "memory");                       \
    }                                                                          \
} while (0)

#define CP_BULK(dst, src, bytes, mbar) \
    asm volatile("cp.async.bulk.shared::cluster.global.mbarrier::complete_tx::bytes [%0], [%1], %2, [%3];" \
        :: "r"(dst), "l"(src), "r"(bytes), "r"(mbar) : "memory")

#define FENCE_PROXY() asm volatile("fence.proxy.async.shared::cta;" ::: "memory")

#define LDSM_X4(r0, r1, r2, r3, addr) \
    asm volatile("ldmatrix.sync.aligned.m8n8.x4.shared.b16 {%0,%1,%2,%3}, [%4];" \
        : "=r"(r0), "=r"(r1), "=r"(r2), "=r"(r3) : "r"(addr))

__device__ __forceinline__ void mma16816h(float* d, const unsigned* a, const unsigned* b) {
    asm volatile("mma.sync.aligned.m16n8k16.row.col.f32.f16.f16.f32 "
        "{%0,%1,%2,%3}, {%4,%5,%6,%7}, {%8,%9}, {%0,%1,%2,%3};"
        : "+f"(d[0]), "+f"(d[1]), "+f"(d[2]), "+f"(d[3])
        : "r"(a[0]), "r"(a[1]), "r"(a[2]), "r"(a[3]), "r"(b[0]), "r"(b[1]));
}

// pack 2 floats -> fp16x2 bits
__device__ __forceinline__ unsigned pk2h(float x, float y) {
    __half2 h = __floats2half2_rn(x, y);
    return *reinterpret_cast<unsigned*>(&h);
}

// ---------------------------------------------------------------------------
// Kernel: conv_w — Wv and Wo (1024x1024 fp32 each) -> fp16 B panels.
// ---------------------------------------------------------------------------
#define CONVW_BLOCKS ((DD*128)/256)
__global__ __launch_bounds__(256)
void conv_w(const float* __restrict__ w0, const float* __restrict__ w1)
{
    int bx = blockIdx.x;
    int which = bx >= CONVW_BLOCKS;
    const float* src = which ? w1 : w0;
    uint4* dst = which ? g_bhi2 : g_bhi;
    int id = (bx - which*CONVW_BLOCKS) * 256 + threadIdx.x;

    int n = id >> 7;
    int cc = id & 127;
    int c = cc >> 3, cell = cc & 7;
    int k0 = c * 64 + cell * 8;

    const float4* s = (const float4*)(src + (size_t)n * DD + k0);
    float4 a = s[0], b = s[1];

    uint4 H = make_uint4(pk2h(a.x,a.y), pk2h(a.z,a.w), pk2h(b.x,b.y), pk2h(b.z,b.w));
    size_t off16 = ((size_t)c * DD + n) * 8 + (cell ^ (n & 7));
    dst[off16] = H;
}

// ---------------------------------------------------------------------------
// Kernel: mma_gemm — unchanged from R15 (structural floor for this approach)
// ---------------------------------------------------------------------------
#define TILE_A   16384
#define TILE_BB  32768
#define STG      (TILE_A + TILE_BB)     // 48 KB
#define KBLK     16
#define NSTAGE   4
#define GSMEM    (1024 + NSTAGE*STG)    // 197632
#define NWARP    8

template<int MODE>
__global__ __launch_bounds__(256, 1)
void mma_gemm(const float* __restrict__ bias, const float* __restrict__ X,
              float* __restrict__ Cout)
{
    extern __shared__ char smem[];
    unsigned sb = smem_u32(smem);
    int tid = threadIdx.x, lane = tid & 31, wid = tid >> 5;
    int wm = wid & 1, wn = wid >> 1;
    int bn = blockIdx.x * 256, bm = blockIdx.y * 128;

    if (tid == 0) {
        #pragma unroll
        for (int s = 0; s < NSTAGE; ++s) {
            MBAR_INIT(sb + 8  + 16*s, 1);
            MBAR_INIT(sb + 16 + 16*s, NWARP);
        }
        FENCE_PROXY();
    }
    __syncthreads();

    const char* pA = (const char*)g_ahi;
    const char* pB = (MODE == 0) ? (const char*)g_bhi : (const char*)g_bhi2;

    auto issue = [&](int kb, int s) {
        unsigned st = sb + 1024 + s * STG;
        unsigned fm = sb + 8 + 16*s;
        size_t aoff = ((size_t)kb * BL + bm) * 128;
        size_t boff = ((size_t)kb * DD + bn) * 128;
        MBAR_EXPECT_TX(fm, STG);
        CP_BULK(st,          pA + aoff, TILE_A,  fm);
        CP_BULK(st + TILE_A, pB + boff, TILE_BB, fm);
    };
    if (tid == 0) {
        #pragma unroll
        for (int s = 0; s < NSTAGE - 1; ++s) issue(s, s);
    }

    float acc[4][8][4];
    #pragma unroll
    for (int i = 0; i < 4; ++i)
        #pragma unroll
        for (int j = 0; j < 8; ++j)
            #pragma unroll
            for (int q = 0; q < 4; ++q) acc[i][j][q] = 0.f;

    int rl = (lane & 7) + ((lane >> 3) & 1) * 8;
    int cs = lane >> 4;

    int rA[4], sA[4], rB[4], sB[4];
    #pragma unroll
    for (int i = 0; i < 4; ++i) { int r = wm*64 + i*16 + rl; rA[i] = r*128; sA[i] = r & 7; }
    #pragma unroll
    for (int j = 0; j < 4; ++j) { int r = wn*64 + j*16 + rl; rB[j] = r*128; sB[j] = r & 7; }

    unsigned opA[2][16], opB[2][16];

    auto load_ops = [&](unsigned bA, unsigned bBp, int ks, unsigned* A, unsigned* B) {
        int cc = ks * 2 + cs;
        #pragma unroll
        for (int i = 0; i < 4; ++i) {
            unsigned off = rA[i] + ((cc ^ sA[i]) << 4);
            LDSM_X4(A[i*4+0], A[i*4+1], A[i*4+2], A[i*4+3], bA + off);
        }
        #pragma unroll
        for (int j = 0; j < 4; ++j) {
            unsigned off = rB[j] + ((cc ^ sB[j]) << 4);
            unsigned r0, r1, r2, r3;
            LDSM_X4(r0, r1, r2, r3, bBp + off);
            B[j*4+0] = r0; B[j*4+1] = r2; B[j*4+2] = r1; B[j*4+3] = r3;
        }
    };

    auto do_mma = [&](const unsigned* A, const unsigned* B) {
        #pragma unroll
        for (int jt = 0; jt < 4; ++jt)
            #pragma unroll
            for (int h = 0; h < 2; ++h) {
                const unsigned* Bf = B + jt*4 + h*2;
                #pragma unroll
                for (int i = 0; i < 4; ++i)
                    mma16816h(acc[i][jt*2+h], A + i*4, Bf);
            }
    };

    for (int kb = 0; kb < KBLK; ++kb) {
        int s  = kb % NSTAGE;
        int ph = (kb / NSTAGE) & 1;
        MBAR_WAIT(sb + 8 + 16*s, ph);
        unsigned st = sb + 1024 + s * STG;
        unsigned bA = st, bBp = st + TILE_A;

        load_ops(bA, bBp, 0, opA[0], opB[0]);
        #pragma unroll
        for (int ks = 0; ks < 4; ++ks) {
            int cur = ks & 1;
            if (ks < 3) load_ops(bA, bBp, ks + 1, opA[cur^1], opB[cur^1]);
            do_mma(opA[cur], opB[cur]);
        }

        if (lane == 0) MBAR_ARRIVE(sb + 16 + 16*s);
        if (tid == 0 && kb + NSTAGE - 1 < KBLK) {
            MBAR_WAIT(sb + 16 + 16*s, ph);
            issue(kb + NSTAGE - 1, (kb + NSTAGE - 1) % NSTAGE);
        }
    }

    #pragma unroll
    for (int i = 0; i < 4; ++i) {
        int r0 = bm + wm*64 + i*16 + (lane >> 2);
        #pragma unroll
        for (int j = 0; j < 8; ++j) {
            int col = bn + wn*64 + j*8 + (lane & 3)*2;
            float2 b2 = *(const float2*)(bias + col);
            float2 v0 = make_float2(acc[i][j][0] + b2.x, acc[i][j][1] + b2.y);
            float2 v1 = make_float2(acc[i][j][2] + b2.x, acc[i][j][3] + b2.y);
            if (MODE == 1) {
                float2 x0 = *(const float2*)(X + (size_t)r0*DD + col);
                float2 x1 = *(const float2*)(X + (size_t)(r0+8)*DD + col);
                v0.x += x0.x; v0.y += x0.y;
                v1.x += x1.x; v1.y += x1.y;
                *(float2*)(Cout + (size_t)r0*DD + col)     = v0;
                *(float2*)(Cout + (size_t)(r0+8)*DD + col) = v1;
            } else {
                *(__half2*)(&g_valh[(size_t)r0*DD + col])     = __floats2half2_rn(v0.x, v0.y);
                *(__half2*)(&g_valh[(size_t)(r0+8)*DD + col]) = __floats2half2_rn(v1.x, v1.y);
            }
        }
    }

    __syncthreads();
    if (tid == 0) {
        #pragma unroll
        for (int s = 0; s < NSTAGE; ++s) {
            MBAR_INVAL(sb + 8  + 16*s);
            MBAR_INVAL(sb + 16 + 16*s);
        }
    }
}

// ---------------------------------------------------------------------------
// Kernel: proj — content key/query + combiner for 16 tokens per block,
// FUSED with x -> fp16 A-panel conversion. Dynamic smem (67 KB).
// ---------------------------------------------------------------------------
#define PT 16
#define PROJ_SMEM (PT*DD*4 + 2*PT*16*4 + PT*16*4)   // 68608
__global__ __launch_bounds__(256)
void proj_kernel(const float* __restrict__ x,
                 const float* __restrict__ Wck, const float* __restrict__ bck,
                 const float* __restrict__ Wcq, const float* __restrict__ bcq,
                 const float* __restrict__ Wc,  const float* __restrict__ bc,
                 const float* __restrict__ pos_key)
{
    extern __shared__ float psm[];
    float (*xs)[DD]        = (float(*)[DD])psm;                       // PT x DD
    float (*dots)[PT][16]  = (float(*)[PT][16])(psm + PT*DD);         // 2 x PT x 16
    float (*pos_s)[16]     = (float(*)[16])(psm + PT*DD + 2*PT*16);   // PT x 16

    int t0   = blockIdx.x * PT;
    int tid  = threadIdx.x;
    int lane = tid & 31;
    int warp = tid >> 5;

    #pragma unroll
    for (int i = tid; i < PT*DD/4; i += 256)
        ((float4*)&xs[0][0])[i] = ((const float4*)(x + (size_t)t0*DD))[i];
    {
        int tt = tid >> 4, k = tid & 15;     // 256 threads = PT*16 exactly
        int l = (t0 + tt) & (LL-1);
        pos_s[tt][k] = pos_key[l*KK + k];
    }
    __syncthreads();

    // --- fused conv: 16 rows x 16 threads; each thread 8 (chunk,cell) slots ---
    {
        int tt = tid >> 4;
        int t  = t0 + tt;
        int j  = tid & 15;
        #pragma unroll
        for (int q = 0; q < 8; ++q) {
            int slot = j + q*16;            // 0..127
            int c = slot >> 3, cell = slot & 7;
            int k0 = c*64 + cell*8;
            const float* v = &xs[tt][k0];
            uint4 H = make_uint4(pk2h(v[0],v[1]), pk2h(v[2],v[3]),
                                 pk2h(v[4],v[5]), pk2h(v[6],v[7]));
            size_t off16 = ((size_t)c * BL + t) * 8 + (cell ^ (t & 7));
            g_ahi[off16] = H;
        }
    }

    // --- 32 dot products; each warp does 4 (sequential — keeps regs low) ---
    #pragma unroll 1
    for (int oo = 0; oo < 4; ++oo) {
        int o = warp + oo*8;
        const float* W = (o < 16) ? (Wck + (size_t)o*DD) : (Wcq + (size_t)(o-16)*DD);
        float bias_o   = (o < 16) ? bck[o] : bcq[o-16];
        float wreg[32];
        #pragma unroll
        for (int i = 0; i < 32; ++i) wreg[i] = W[lane + 32*i];
        #pragma unroll
        for (int t = 0; t < PT; ++t) {
            float s = 0.f;
            #pragma unroll
            for (int i = 0; i < 32; ++i) s += wreg[i] * xs[t][lane + 32*i];
            #pragma unroll
            for (int off = 16; off; off >>= 1)
                s += __shfl_xor_sync(0xffffffffu, s, off);
            if (lane == 0)
                dots[o >> 4][t][o & 15] = s + bias_o;
        }
    }
    __syncthreads();

    // --- normalize + combiner + normalize: each warp handles 2 tokens ---
    #pragma unroll
    for (int ti = 0; ti < 2; ++ti) {
        int t    = warp*2 + ti;
        int path = lane >> 4;
        int l16  = lane & 15;

        float v = dots[path][t][l16];
        float ss = v*v;
        #pragma unroll
        for (int off = 8; off; off >>= 1)
            ss += __shfl_xor_sync(0xffffffffu, ss, off, 16);
        float cnv = v / fmaxf(sqrtf(ss), 1e-12f);

        float s = bc[l16];
        #pragma unroll
        for (int j = 0; j < 16; ++j) {
            float cj = __shfl_sync(0xffffffffu, cnv, j, 16);
            s += Wc[l16*32 + j]      * pos_s[t][j];
            s += Wc[l16*32 + 16 + j] * cj;
        }
        s = tanhf(s);
        float sq = s*s;
        #pragma unroll
        for (int off = 8; off; off >>= 1)
            sq += __shfl_xor_sync(0xffffffffu, sq, off, 16);
        float outv = s / fmaxf(sqrtf(sq), 1e-12f);
        float* dst = (path == 0) ? g_ck : g_cq;
        dst[(t0 + t)*KK + l16] = outv;
    }
}

// ---------------------------------------------------------------------------
// Kernel: per-chunk partial state (fp16 S out), 2 d-cols/thread, t x4 unroll.
// grid = (DD/256, NCH, BB), 128 threads.
// ---------------------------------------------------------------------------
__global__ __launch_bounds__(128)
void scan_partial()
{
    int d2 = blockIdx.x * 128 + threadIdx.x;
    int c = blockIdx.y;
    int b = blockIdx.z;
    __shared__ float cks[LC*KK];

    int base_t = b*LL + c*LC;
    for (int i = threadIdx.x; i < LC*KK; i += 128)
        cks[i] = g_ck[base_t*KK + i];
    __syncthreads();

    float sx[KK], sy[KK];
    #pragma unroll
    for (int k = 0; k < KK; ++k) { sx[k] = 0.f; sy[k] = 0.f; }

    const __half2* vp = (const __half2*)(g_valh + (size_t)base_t*DD) + d2;
    #pragma unroll 1
    for (int t = 0; t < LC; t += 4) {
        float2 v[4];
        #pragma unroll
        for (int u = 0; u < 4; ++u)
            v[u] = __half22float2(vp[(size_t)(t+u)*(DD/2)]);
        #pragma unroll
        for (int u = 0; u < 4; ++u) {
            #pragma unroll
            for (int k = 0; k < KK; ++k) {
                float ckv = cks[(t+u)*KK + k];
                sx[k] += v[u].x * ckv;
                sy[k] += v[u].y * ckv;
            }
        }
    }
    __half2* Sp = (__half2*)g_Sh + ((size_t)(b*NCH + c)*KK)*(DD/2) + d2;
    #pragma unroll
    for (int k = 0; k < KK; ++k)
        Sp[(size_t)k*(DD/2)] = __floats2half2_rn(sx[k], sy[k]);
}

// ---------------------------------------------------------------------------
// Kernel: exclusive prefix over 128 chunks (fp16 storage, fp32 accumulate).
// One thread per (b, k, d-pair). 32768 threads.
// ---------------------------------------------------------------------------
__global__ __launch_bounds__(256)
void scan_prefix()
{
    int id  = blockIdx.x * 256 + threadIdx.x;   // 0 .. BB*KK*DD/2-1
    int b   = id >> 13;                          // / (KK*DD/2 = 8192)
    int rem = id & 8191;
    __half2* base = (__half2*)g_Sh + (size_t)b*NCH*KK*(DD/2) + rem;

    float rx = 0.f, ry = 0.f;
    #pragma unroll 1
    for (int h = 0; h < 4; ++h) {
        __half2 v[NCH/4];
        #pragma unroll
        for (int c = 0; c < NCH/4; ++c)
            v[c] = base[(size_t)(h*(NCH/4) + c)*KK*(DD/2)];
        #pragma unroll
        for (int c = 0; c < NCH/4; ++c) {
            float2 f = __half22float2(v[c]);
            base[(size_t)(h*(NCH/4) + c)*KK*(DD/2)] = __floats2half2_rn(rx, ry);
            rx += f.x; ry += f.y;
        }
    }
}

// ---------------------------------------------------------------------------
// Kernel: apply scan (fp16 S in), 2 d-cols/thread, t x4 unroll -> g_reth.
// grid = (DD/256, NCH, BB), 128 threads.
// ---------------------------------------------------------------------------
__global__ __launch_bounds__(128)
void scan_apply()
{
    int d2 = blockIdx.x * 128 + threadIdx.x;
    int c = blockIdx.y;
    int b = blockIdx.z;
    __shared__ float cks[LC*KK];
    __shared__ float cqs[LC*KK];

    int base_t = b*LL + c*LC;
    for (int i = threadIdx.x; i < LC*KK; i += 128) {
        cks[i] = g_ck[base_t*KK + i];
        cqs[i] = g_cq[base_t*KK + i];
    }
    __syncthreads();

    float sx[KK], sy[KK];
    const __half2* Sp = (const __half2*)g_Sh + ((size_t)(b*NCH + c)*KK)*(DD/2) + d2;
    #pragma unroll
    for (int k = 0; k < KK; ++k) {
        float2 s = __half22float2(Sp[(size_t)k*(DD/2)]);
        sx[k] = s.x; sy[k] = s.y;
    }

    const __half2* vp = (const __half2*)(g_valh + (size_t)base_t*DD) + d2;
    __half2*       rp = (__half2*)(g_reth + (size_t)base_t*DD) + d2;
    #pragma unroll 1
    for (int t = 0; t < LC; t += 4) {
        float2 v[4];
        #pragma unroll
        for (int u = 0; u < 4; ++u)
            v[u] = __half22float2(vp[(size_t)(t+u)*(DD/2)]);
        #pragma unroll
        for (int u = 0; u < 4; ++u) {
            float ax = 0.f, ay = 0.f;
            #pragma unroll
            for (int k = 0; k < KK; ++k) {
                float ckv = cks[(t+u)*KK + k];
                float cqv = cqs[(t+u)*KK + k];
                sx[k] += v[u].x * ckv;
                sy[k] += v[u].y * ckv;
                ax    += cqv * sx[k];
                ay    += cqv * sy[k];
            }
            rp[(size_t)(t+u)*(DD/2)] = __floats2half2_rn(ax * 0.25f, ay * 0.25f);
        }
    }
}

// ---------------------------------------------------------------------------
// Kernel: LayerNorm on g_reth (fp16 in), fused fp16 panel output
// ---------------------------------------------------------------------------
__global__ __launch_bounds__(256)
void layernorm_conv(const float* __restrict__ gam, const float* __restrict__ bet)
{
    int t = blockIdx.x;
    const __half2* row = (const __half2*)(g_reth + (size_t)t*DD);
    __shared__ float sh[DD];
    __shared__ float ws[8], wq[8];
    __shared__ float s_mean, s_rstd;

    int tid  = threadIdx.x;
    int lane = tid & 31;
    int wid  = tid >> 5;

    float2 a = __half22float2(row[tid*2]);
    float2 b = __half22float2(row[tid*2 + 1]);
    sh[tid*4+0] = a.x; sh[tid*4+1] = a.y; sh[tid*4+2] = b.x; sh[tid*4+3] = b.y;
    float s = a.x + a.y + b.x + b.y;
    float q = a.x*a.x + a.y*a.y + b.x*b.x + b.y*b.y;
    #pragma unroll
    for (int off = 16; off; off >>= 1) {
        s += __shfl_xor_sync(0xffffffffu, s, off);
        q += __shfl_xor_sync(0xffffffffu, q, off);
    }
    if (lane == 0) { ws[wid] = s; wq[wid] = q; }
    __syncthreads();
    if (tid == 0) {
        float S = 0.f, Q = 0.f;
        #pragma unroll
        for (int i = 0; i < 8; ++i) { S += ws[i]; Q += wq[i]; }
        float m   = S / (float)DD;
        float var = Q / (float)DD - m*m;
        s_mean = m;
        s_rstd = rsqrtf(var + 1e-5f);
    }
    __syncthreads();
    float m = s_mean, r = s_rstd;

    int d0 = tid * 4;
    float nv[4];
    #pragma unroll
    for (int i = 0; i < 4; ++i) {
        int d = d0 + i;
        nv[i] = (sh[d] - m) * r * gam[d] + bet[d];
    }
    int c8    = d0 >> 6;
    int inrow = ((d0 & 63) * 2) ^ ((t & 7) << 4);
    size_t byteoff = ((size_t)c8 * BL + t) * 128 + inrow;
    *(uint2*)((char*)g_ahi + byteoff) = make_uint2(pk2h(nv[0],nv[1]), pk2h(nv[2],nv[3]));
}

// ---------------------------------------------------------------------------
extern "C" void kernel_launch(void* const* d_in, const int* in_sizes, int n_in,
                              void* d_out, int out_size)
{
    const float* x       = (const float*)d_in[0];
    const float* Wv      = (const float*)d_in[1];
    const float* bv      = (const float*)d_in[2];
    const float* Wck     = (const float*)d_in[3];
    const float* bck     = (const float*)d_in[4];
    const float* Wc      = (const float*)d_in[5];
    const float* bc      = (const float*)d_in[6];
    const float* Wcq     = (const float*)d_in[7];
    const float* bcq     = (const float*)d_in[8];
    const float* ln_g    = (const float*)d_in[9];
    const float* ln_b    = (const float*)d_in[10];
    const float* Wo      = (const float*)d_in[11];
    const float* bo      = (const float*)d_in[12];
    const float* pos_key = (const float*)d_in[13];
    float* out = (float*)d_out;

    cudaFuncSetAttribute(mma_gemm<0>, cudaFuncAttributeMaxDynamicSharedMemorySize, GSMEM);
    cudaFuncSetAttribute(mma_gemm<1>, cudaFuncAttributeMaxDynamicSharedMemorySize, GSMEM);
    cudaFuncSetAttribute(proj_kernel, cudaFuncAttributeMaxDynamicSharedMemorySize, PROJ_SMEM);

    // both weight panels in one launch
    conv_w<<<2*CONVW_BLOCKS, 256>>>(Wv, Wo);

    // proj + fused x->panel conversion (16 tokens/block)
    proj_kernel<<<BL/PT, 256, PROJ_SMEM>>>(x, Wck, bck, Wcq, bcq, Wc, bc, pos_key);

    // value = x @ Wv^T + bv  (written as fp16 into g_valh)
    mma_gemm<0><<<dim3(DD/256, BL/128), 256, GSMEM>>>(bv, nullptr, nullptr);

    // chunked causal scan (128 chunks of 16 tokens, fp16 state)
    {
        dim3 grid(DD/256, NCH, BB);
        scan_partial<<<grid, 128>>>();
        scan_prefix<<<(BB*KK*DD/2)/256, 256>>>();
        scan_apply<<<grid, 128>>>();
    }

    // LayerNorm + fused fp16 conversion into A panel
    layernorm_conv<<<BL, 256>>>(ln_g, ln_b);

    // out = x + normed @ Wo^T + bo
    mma_gemm<1><<<dim3(DD/256, BL/128), 256, GSMEM>>>(bo, x, out);
}

// round 17
// speedup vs baseline: 1.0084x; 1.0084x over previous
#include <cuda_runtime.h>
#include <cuda_bf16.h>
#include <cuda_fp16.h>
#include <math.h>

// Problem constants
#define BB   4
#define LL   2048
#define DD   1024
#define KK   16
#define BL   (BB*LL)        // 8192 tokens
#define NCH  64             // scan chunks
#define LC   (LL/NCH)       // 32 tokens per chunk

// ---------------------------------------------------------------------------
// Scratch (no allocation allowed -> __device__ globals)
// ---------------------------------------------------------------------------
__device__ __half g_valh[BL*DD];            // 16 MB (value, fp16)
__device__ __half g_reth[BL*DD];            // 16 MB (retrieved, fp16, pre-LN)
__device__ float g_ck   [BL*KK];
__device__ float g_cq   [BL*KK];
__device__ float g_S    [BB*NCH*KK*DD];     // 16 MB chunk states

// fp16 operand panels, chunk-major, swizzled (cell ^ (row&7)) layout.
__device__ uint4 g_ahi[(16*8192*128)/16];   // 16 MB (x, later normed)
__device__ uint4 g_bhi[(16*1024*128)/16];   // 2 MB  (Wv)
__device__ uint4 g_bhi2[(16*1024*128)/16];  // 2 MB  (Wo)

// ---------------------------------------------------------------------------
// PTX helpers (base sm_90/sm_80 features only — target is plain sm_100!)
// ---------------------------------------------------------------------------
__device__ __forceinline__ unsigned smem_u32(const void* p) {
    unsigned a;
    asm("{ .reg .u64 t; cvta.to.shared.u64 t, %1; cvt.u32.u64 %0, t; }" : "=r"(a) : "l"(p));
    return a;
}

#define MBAR_INIT(addr, cnt) \
    asm volatile("mbarrier.init.shared.b64 [%0], %1;" :: "r"(addr), "r"(cnt) : "memory")
#define MBAR_INVAL(addr) \
    asm volatile("mbarrier.inval.shared.b64 [%0];" :: "r"(addr) : "memory")
#define MBAR_EXPECT_TX(addr, bytes) \
    asm volatile("mbarrier.arrive.expect_tx.shared.b64 _, [%0], %1;" :: "r"(addr), "r"(bytes) : "memory")
#define MBAR_ARRIVE(addr) \
    asm volatile("mbarrier.arrive.shared.b64 _, [%0];" :: "r"(addr) : "memory")

#define MBAR_WAIT(addr, par) do {                                              \
    unsigned _m = (addr), _p = (par), _d;                                      \
    asm volatile("{\n\t.reg .pred p;\n\t"                                      \
        "mbarrier.try_wait.parity.acquire.cta.shared::cta.b64 p, [%1], %2;\n\t"\
        "selp.b32 %0, 1, 0, p;\n\t}"                                           \
        : "=r"(_d) : "r"(_m), "r"(_p) : "memory");                             \
    if (!_d) {                                                                 \
        asm volatile("{\n\t.reg .pred P1;\n\t"                                 \
            "W%=:\n\t"                                                         \
            "mbarrier.try_wait.parity.acquire.cta.shared::cta.b64 P1, [%0], %1, 0x989680;\n\t" \
            "@P1 bra.uni D%=;\n\t"                                             \
            "bra.uni W%=;\n\t"                                                 \
            "D%=:\n\t}" :: "r"(_m), "r"(_p) : "memory");                       \
    }                                                                          \
} while (0)

#define CP_BULK(dst, src, bytes, mbar) \
    asm volatile("cp.async.bulk.shared::cluster.global.mbarrier::complete_tx::bytes [%0], [%1], %2, [%3];" \
        :: "r"(dst), "l"(src), "r"(bytes), "r"(mbar) : "memory")

#define FENCE_PROXY() asm volatile("fence.proxy.async.shared::cta;" ::: "memory")

#define LDSM_X4(r0, r1, r2, r3, addr) \
    asm volatile("ldmatrix.sync.aligned.m8n8.x4.shared.b16 {%0,%1,%2,%3}, [%4];" \
        : "=r"(r0), "=r"(r1), "=r"(r2), "=r"(r3) : "r"(addr))

__device__ __forceinline__ void mma16816h(float* d, const unsigned* a, const unsigned* b) {
    asm volatile("mma.sync.aligned.m16n8k16.row.col.f32.f16.f16.f32 "
        "{%0,%1,%2,%3}, {%4,%5,%6,%7}, {%8,%9}, {%0,%1,%2,%3};"
        : "+f"(d[0]), "+f"(d[1]), "+f"(d[2]), "+f"(d[3])
        : "r"(a[0]), "r"(a[1]), "r"(a[2]), "r"(a[3]), "r"(b[0]), "r"(b[1]));
}

// pack 2 floats -> fp16x2 bits
__device__ __forceinline__ unsigned pk2h(float x, float y) {
    __half2 h = __floats2half2_rn(x, y);
    return *reinterpret_cast<unsigned*>(&h);
}

// ---------------------------------------------------------------------------
// Kernel: conv_w — Wv and Wo (1024x1024 fp32 each) -> fp16 B panels.
// ---------------------------------------------------------------------------
#define CONVW_BLOCKS ((DD*128)/256)
__global__ __launch_bounds__(256)
void conv_w(const float* __restrict__ w0, const float* __restrict__ w1)
{
    int bx = blockIdx.x;
    int which = bx >= CONVW_BLOCKS;
    const float* src = which ? w1 : w0;
    uint4* dst = which ? g_bhi2 : g_bhi;
    int id = (bx - which*CONVW_BLOCKS) * 256 + threadIdx.x;

    int n = id >> 7;
    int cc = id & 127;
    int c = cc >> 3, cell = cc & 7;
    int k0 = c * 64 + cell * 8;

    const float4* s = (const float4*)(src + (size_t)n * DD + k0);
    float4 a = s[0], b = s[1];

    uint4 H = make_uint4(pk2h(a.x,a.y), pk2h(a.z,a.w), pk2h(b.x,b.y), pk2h(b.z,b.w));
    size_t off16 = ((size_t)c * DD + n) * 8 + (cell ^ (n & 7));
    dst[off16] = H;
}

// ---------------------------------------------------------------------------
// Kernel: mma_gemm — unchanged (structural floor for this approach)
// ---------------------------------------------------------------------------
#define TILE_A   16384
#define TILE_BB  32768
#define STG      (TILE_A + TILE_BB)     // 48 KB
#define KBLK     16
#define NSTAGE   4
#define GSMEM    (1024 + NSTAGE*STG)    // 197632
#define NWARP    8

template<int MODE>
__global__ __launch_bounds__(256, 1)
void mma_gemm(const float* __restrict__ bias, const float* __restrict__ X,
              float* __restrict__ Cout)
{
    extern __shared__ char smem[];
    unsigned sb = smem_u32(smem);
    int tid = threadIdx.x, lane = tid & 31, wid = tid >> 5;
    int wm = wid & 1, wn = wid >> 1;
    int bn = blockIdx.x * 256, bm = blockIdx.y * 128;

    if (tid == 0) {
        #pragma unroll
        for (int s = 0; s < NSTAGE; ++s) {
            MBAR_INIT(sb + 8  + 16*s, 1);
            MBAR_INIT(sb + 16 + 16*s, NWARP);
        }
        FENCE_PROXY();
    }
    __syncthreads();

    const char* pA = (const char*)g_ahi;
    const char* pB = (MODE == 0) ? (const char*)g_bhi : (const char*)g_bhi2;

    auto issue = [&](int kb, int s) {
        unsigned st = sb + 1024 + s * STG;
        unsigned fm = sb + 8 + 16*s;
        size_t aoff = ((size_t)kb * BL + bm) * 128;
        size_t boff = ((size_t)kb * DD + bn) * 128;
        MBAR_EXPECT_TX(fm, STG);
        CP_BULK(st,          pA + aoff, TILE_A,  fm);
        CP_BULK(st + TILE_A, pB + boff, TILE_BB, fm);
    };
    if (tid == 0) {
        #pragma unroll
        for (int s = 0; s < NSTAGE - 1; ++s) issue(s, s);
    }

    float acc[4][8][4];
    #pragma unroll
    for (int i = 0; i < 4; ++i)
        #pragma unroll
        for (int j = 0; j < 8; ++j)
            #pragma unroll
            for (int q = 0; q < 4; ++q) acc[i][j][q] = 0.f;

    int rl = (lane & 7) + ((lane >> 3) & 1) * 8;
    int cs = lane >> 4;

    int rA[4], sA[4], rB[4], sB[4];
    #pragma unroll
    for (int i = 0; i < 4; ++i) { int r = wm*64 + i*16 + rl; rA[i] = r*128; sA[i] = r & 7; }
    #pragma unroll
    for (int j = 0; j < 4; ++j) { int r = wn*64 + j*16 + rl; rB[j] = r*128; sB[j] = r & 7; }

    unsigned opA[2][16], opB[2][16];

    auto load_ops = [&](unsigned bA, unsigned bBp, int ks, unsigned* A, unsigned* B) {
        int cc = ks * 2 + cs;
        #pragma unroll
        for (int i = 0; i < 4; ++i) {
            unsigned off = rA[i] + ((cc ^ sA[i]) << 4);
            LDSM_X4(A[i*4+0], A[i*4+1], A[i*4+2], A[i*4+3], bA + off);
        }
        #pragma unroll
        for (int j = 0; j < 4; ++j) {
            unsigned off = rB[j] + ((cc ^ sB[j]) << 4);
            unsigned r0, r1, r2, r3;
            LDSM_X4(r0, r1, r2, r3, bBp + off);
            B[j*4+0] = r0; B[j*4+1] = r2; B[j*4+2] = r1; B[j*4+3] = r3;
        }
    };

    auto do_mma = [&](const unsigned* A, const unsigned* B) {
        #pragma unroll
        for (int jt = 0; jt < 4; ++jt)
            #pragma unroll
            for (int h = 0; h < 2; ++h) {
                const unsigned* Bf = B + jt*4 + h*2;
                #pragma unroll
                for (int i = 0; i < 4; ++i)
                    mma16816h(acc[i][jt*2+h], A + i*4, Bf);
            }
    };

    for (int kb = 0; kb < KBLK; ++kb) {
        int s  = kb % NSTAGE;
        int ph = (kb / NSTAGE) & 1;
        MBAR_WAIT(sb + 8 + 16*s, ph);
        unsigned st = sb + 1024 + s * STG;
        unsigned bA = st, bBp = st + TILE_A;

        load_ops(bA, bBp, 0, opA[0], opB[0]);
        #pragma unroll
        for (int ks = 0; ks < 4; ++ks) {
            int cur = ks & 1;
            if (ks < 3) load_ops(bA, bBp, ks + 1, opA[cur^1], opB[cur^1]);
            do_mma(opA[cur], opB[cur]);
        }

        if (lane == 0) MBAR_ARRIVE(sb + 16 + 16*s);
        if (tid == 0 && kb + NSTAGE - 1 < KBLK) {
            MBAR_WAIT(sb + 16 + 16*s, ph);
            issue(kb + NSTAGE - 1, (kb + NSTAGE - 1) % NSTAGE);
        }
    }

    #pragma unroll
    for (int i = 0; i < 4; ++i) {
        int r0 = bm + wm*64 + i*16 + (lane >> 2);
        #pragma unroll
        for (int j = 0; j < 8; ++j) {
            int col = bn + wn*64 + j*8 + (lane & 3)*2;
            float2 b2 = *(const float2*)(bias + col);
            float2 v0 = make_float2(acc[i][j][0] + b2.x, acc[i][j][1] + b2.y);
            float2 v1 = make_float2(acc[i][j][2] + b2.x, acc[i][j][3] + b2.y);
            if (MODE == 1) {
                float2 x0 = *(const float2*)(X + (size_t)r0*DD + col);
                float2 x1 = *(const float2*)(X + (size_t)(r0+8)*DD + col);
                v0.x += x0.x; v0.y += x0.y;
                v1.x += x1.x; v1.y += x1.y;
                *(float2*)(Cout + (size_t)r0*DD + col)     = v0;
                *(float2*)(Cout + (size_t)(r0+8)*DD + col) = v1;
            } else {
                *(__half2*)(&g_valh[(size_t)r0*DD + col])     = __floats2half2_rn(v0.x, v0.y);
                *(__half2*)(&g_valh[(size_t)(r0+8)*DD + col]) = __floats2half2_rn(v1.x, v1.y);
            }
        }
    }

    __syncthreads();
    if (tid == 0) {
        #pragma unroll
        for (int s = 0; s < NSTAGE; ++s) {
            MBAR_INVAL(sb + 8  + 16*s);
            MBAR_INVAL(sb + 16 + 16*s);
        }
    }
}

// ---------------------------------------------------------------------------
// Kernel: proj — content key/query + combiner for 8 tokens per block,
// FUSED with x -> fp16 A-panel conversion (reads x once).
// ---------------------------------------------------------------------------
#define PT 8
__global__ __launch_bounds__(256)
void proj_kernel(const float* __restrict__ x,
                 const float* __restrict__ Wck, const float* __restrict__ bck,
                 const float* __restrict__ Wcq, const float* __restrict__ bcq,
                 const float* __restrict__ Wc,  const float* __restrict__ bc,
                 const float* __restrict__ pos_key)
{
    int t0   = blockIdx.x * PT;
    int tid  = threadIdx.x;
    int lane = tid & 31;
    int warp = tid >> 5;

    __shared__ float xs[PT][DD];
    __shared__ float dots[2][PT][16];
    __shared__ float pos_s[PT][16];

    #pragma unroll
    for (int i = tid; i < PT*DD/4; i += 256)
        ((float4*)&xs[0][0])[i] = ((const float4*)(x + (size_t)t0*DD))[i];
    if (tid < PT*16) {
        int tt = tid >> 4, k = tid & 15;
        int l = (t0 + tt) & (LL-1);
        pos_s[tt][k] = pos_key[l*KK + k];
    }
    __syncthreads();

    // --- fused conv: emit fp16 panel rows ---
    {
        int tt   = tid >> 5;
        int t    = t0 + tt;
        int cell = lane & 7;
        #pragma unroll
        for (int q = 0; q < 4; ++q) {
            int c  = (lane >> 3) + q*4;
            int k0 = c*64 + cell*8;
            const float* v = &xs[tt][k0];
            uint4 H = make_uint4(pk2h(v[0],v[1]), pk2h(v[2],v[3]),
                                 pk2h(v[4],v[5]), pk2h(v[6],v[7]));
            size_t off16 = ((size_t)c * BL + t) * 8 + (cell ^ (t & 7));
            g_ahi[off16] = H;
        }
    }

    // --- 32 dot products; each warp does 4 (sequential — keeps regs low) ---
    #pragma unroll 1
    for (int oo = 0; oo < 4; ++oo) {
        int o = warp + oo*8;
        const float* W = (o < 16) ? (Wck + (size_t)o*DD) : (Wcq + (size_t)(o-16)*DD);
        float bias_o   = (o < 16) ? bck[o] : bcq[o-16];
        float wreg[32];
        #pragma unroll
        for (int i = 0; i < 32; ++i) wreg[i] = W[lane + 32*i];
        #pragma unroll
        for (int t = 0; t < PT; ++t) {
            float s = 0.f;
            #pragma unroll
            for (int i = 0; i < 32; ++i) s += wreg[i] * xs[t][lane + 32*i];
            #pragma unroll
            for (int off = 16; off; off >>= 1)
                s += __shfl_xor_sync(0xffffffffu, s, off);
            if (lane == 0)
                dots[o >> 4][t][o & 15] = s + bias_o;
        }
    }
    __syncthreads();

    // --- normalize + combiner + normalize ---
    {
        int t    = warp;
        int path = lane >> 4;
        int l16  = lane & 15;

        float v = dots[path][t][l16];
        float ss = v*v;
        #pragma unroll
        for (int off = 8; off; off >>= 1)
            ss += __shfl_xor_sync(0xffffffffu, ss, off, 16);
        float cnv = v / fmaxf(sqrtf(ss), 1e-12f);

        float s = bc[l16];
        #pragma unroll
        for (int j = 0; j < 16; ++j) {
            float cj = __shfl_sync(0xffffffffu, cnv, j, 16);
            s += Wc[l16*32 + j]      * pos_s[t][j];
            s += Wc[l16*32 + 16 + j] * cj;
        }
        s = tanhf(s);
        float sq = s*s;
        #pragma unroll
        for (int off = 8; off; off >>= 1)
            sq += __shfl_xor_sync(0xffffffffu, sq, off, 16);
        float outv = s / fmaxf(sqrtf(sq), 1e-12f);
        float* dst = (path == 0) ? g_ck : g_cq;
        dst[(t0 + t)*KK + l16] = outv;
    }
}

// ---------------------------------------------------------------------------
// Kernel: per-chunk partial state, 2 d-cols/thread, t x4 unroll, float4 LDS.
// grid = (DD/256, NCH, BB), 128 threads.
// ---------------------------------------------------------------------------
__global__ __launch_bounds__(128)
void scan_partial()
{
    int d2 = blockIdx.x * 128 + threadIdx.x;
    int c = blockIdx.y;
    int b = blockIdx.z;
    __shared__ __align__(16) float cks[LC*KK];

    int base_t = b*LL + c*LC;
    for (int i = threadIdx.x; i < LC*KK; i += 128)
        cks[i] = g_ck[base_t*KK + i];
    __syncthreads();

    float sx[KK], sy[KK];
    #pragma unroll
    for (int k = 0; k < KK; ++k) { sx[k] = 0.f; sy[k] = 0.f; }

    const __half2* vp = (const __half2*)(g_valh + (size_t)base_t*DD) + d2;
    const float4*  ck4 = (const float4*)cks;
    #pragma unroll 1
    for (int t = 0; t < LC; t += 4) {
        float2 v[4];
        #pragma unroll
        for (int u = 0; u < 4; ++u)
            v[u] = __half22float2(vp[(size_t)(t+u)*(DD/2)]);
        #pragma unroll
        for (int u = 0; u < 4; ++u) {
            #pragma unroll
            for (int q = 0; q < 4; ++q) {
                float4 cv = ck4[(t+u)*4 + q];
                sx[q*4+0] += v[u].x * cv.x;  sy[q*4+0] += v[u].y * cv.x;
                sx[q*4+1] += v[u].x * cv.y;  sy[q*4+1] += v[u].y * cv.y;
                sx[q*4+2] += v[u].x * cv.z;  sy[q*4+2] += v[u].y * cv.z;
                sx[q*4+3] += v[u].x * cv.w;  sy[q*4+3] += v[u].y * cv.w;
            }
        }
    }
    float2* Sp = (float2*)(g_S + ((size_t)(b*NCH + c)*KK)*DD) + d2;
    #pragma unroll
    for (int k = 0; k < KK; ++k)
        Sp[(size_t)k*(DD/2)] = make_float2(sx[k], sy[k]);
}

// ---------------------------------------------------------------------------
// Kernel: exclusive prefix over chunks — batched loads for MLP
// ---------------------------------------------------------------------------
__global__ __launch_bounds__(256)
void scan_prefix()
{
    int id  = blockIdx.x * 256 + threadIdx.x;   // 0 .. B*K*D-1
    int b   = id >> 14;
    int rem = id & 16383;
    float* base = g_S + (size_t)b*NCH*KK*DD + rem;

    float run = 0.f;
    #pragma unroll 1
    for (int h = 0; h < 2; ++h) {
        float v[NCH/2];
        #pragma unroll
        for (int c = 0; c < NCH/2; ++c)
            v[c] = base[(size_t)(h*(NCH/2) + c)*KK*DD];
        #pragma unroll
        for (int c = 0; c < NCH/2; ++c) {
            float t = v[c];
            base[(size_t)(h*(NCH/2) + c)*KK*DD] = run;
            run += t;
        }
    }
}

// ---------------------------------------------------------------------------
// Kernel: apply scan, 2 d-cols/thread, t x4 unroll, float4 LDS -> g_reth.
// grid = (DD/256, NCH, BB), 128 threads.
// ---------------------------------------------------------------------------
__global__ __launch_bounds__(128)
void scan_apply()
{
    int d2 = blockIdx.x * 128 + threadIdx.x;
    int c = blockIdx.y;
    int b = blockIdx.z;
    __shared__ __align__(16) float cks[LC*KK];
    __shared__ __align__(16) float cqs[LC*KK];

    int base_t = b*LL + c*LC;
    for (int i = threadIdx.x; i < LC*KK; i += 128) {
        cks[i] = g_ck[base_t*KK + i];
        cqs[i] = g_cq[base_t*KK + i];
    }
    __syncthreads();

    float sx[KK], sy[KK];
    const float2* Sp = (const float2*)(g_S + ((size_t)(b*NCH + c)*KK)*DD) + d2;
    #pragma unroll
    for (int k = 0; k < KK; ++k) {
        float2 s = Sp[(size_t)k*(DD/2)];
        sx[k] = s.x; sy[k] = s.y;
    }

    const __half2* vp = (const __half2*)(g_valh + (size_t)base_t*DD) + d2;
    __half2*       rp = (__half2*)(g_reth + (size_t)base_t*DD) + d2;
    const float4*  ck4 = (const float4*)cks;
    const float4*  cq4 = (const float4*)cqs;
    #pragma unroll 1
    for (int t = 0; t < LC; t += 4) {
        float2 v[4];
        #pragma unroll
        for (int u = 0; u < 4; ++u)
            v[u] = __half22float2(vp[(size_t)(t+u)*(DD/2)]);
        #pragma unroll
        for (int u = 0; u < 4; ++u) {
            float ax = 0.f, ay = 0.f;
            #pragma unroll
            for (int q = 0; q < 4; ++q) {
                float4 cv = ck4[(t+u)*4 + q];
                float4 qv = cq4[(t+u)*4 + q];
                sx[q*4+0] += v[u].x * cv.x;  sy[q*4+0] += v[u].y * cv.x;
                ax += qv.x * sx[q*4+0];      ay += qv.x * sy[q*4+0];
                sx[q*4+1] += v[u].x * cv.y;  sy[q*4+1] += v[u].y * cv.y;
                ax += qv.y * sx[q*4+1];      ay += qv.y * sy[q*4+1];
                sx[q*4+2] += v[u].x * cv.z;  sy[q*4+2] += v[u].y * cv.z;
                ax += qv.z * sx[q*4+2];      ay += qv.z * sy[q*4+2];
                sx[q*4+3] += v[u].x * cv.w;  sy[q*4+3] += v[u].y * cv.w;
                ax += qv.w * sx[q*4+3];      ay += qv.w * sy[q*4+3];
            }
            rp[(size_t)(t+u)*(DD/2)] = __floats2half2_rn(ax * 0.25f, ay * 0.25f);
        }
    }
}

// ---------------------------------------------------------------------------
// Kernel: LayerNorm on g_reth (fp16 in), fused fp16 panel output
// ---------------------------------------------------------------------------
__global__ __launch_bounds__(256)
void layernorm_conv(const float* __restrict__ gam, const float* __restrict__ bet)
{
    int t = blockIdx.x;
    const __half2* row = (const __half2*)(g_reth + (size_t)t*DD);
    __shared__ float sh[DD];
    __shared__ float ws[8], wq[8];
    __shared__ float s_mean, s_rstd;

    int tid  = threadIdx.x;
    int lane = tid & 31;
    int wid  = tid >> 5;

    float2 a = __half22float2(row[tid*2]);
    float2 b = __half22float2(row[tid*2 + 1]);
    sh[tid*4+0] = a.x; sh[tid*4+1] = a.y; sh[tid*4+2] = b.x; sh[tid*4+3] = b.y;
    float s = a.x + a.y + b.x + b.y;
    float q = a.x*a.x + a.y*a.y + b.x*b.x + b.y*b.y;
    #pragma unroll
    for (int off = 16; off; off >>= 1) {
        s += __shfl_xor_sync(0xffffffffu, s, off);
        q += __shfl_xor_sync(0xffffffffu, q, off);
    }
    if (lane == 0) { ws[wid] = s; wq[wid] = q; }
    __syncthreads();
    if (tid == 0) {
        float S = 0.f, Q = 0.f;
        #pragma unroll
        for (int i = 0; i < 8; ++i) { S += ws[i]; Q += wq[i]; }
        float m   = S / (float)DD;
        float var = Q / (float)DD - m*m;
        s_mean = m;
        s_rstd = rsqrtf(var + 1e-5f);
    }
    __syncthreads();
    float m = s_mean, r = s_rstd;

    int d0 = tid * 4;
    float nv[4];
    #pragma unroll
    for (int i = 0; i < 4; ++i) {
        int d = d0 + i;
        nv[i] = (sh[d] - m) * r * gam[d] + bet[d];
    }
    int c8    = d0 >> 6;
    int inrow = ((d0 & 63) * 2) ^ ((t & 7) << 4);
    size_t byteoff = ((size_t)c8 * BL + t) * 128 + inrow;
    *(uint2*)((char*)g_ahi + byteoff) = make_uint2(pk2h(nv[0],nv[1]), pk2h(nv[2],nv[3]));
}

// ---------------------------------------------------------------------------
extern "C" void kernel_launch(void* const* d_in, const int* in_sizes, int n_in,
                              void* d_out, int out_size)
{
    const float* x       = (const float*)d_in[0];
    const float* Wv      = (const float*)d_in[1];
    const float* bv      = (const float*)d_in[2];
    const float* Wck     = (const float*)d_in[3];
    const float* bck     = (const float*)d_in[4];
    const float* Wc      = (const float*)d_in[5];
    const float* bc      = (const float*)d_in[6];
    const float* Wcq     = (const float*)d_in[7];
    const float* bcq     = (const float*)d_in[8];
    const float* ln_g    = (const float*)d_in[9];
    const float* ln_b    = (const float*)d_in[10];
    const float* Wo      = (const float*)d_in[11];
    const float* bo      = (const float*)d_in[12];
    const float* pos_key = (const float*)d_in[13];
    float* out = (float*)d_out;

    cudaFuncSetAttribute(mma_gemm<0>, cudaFuncAttributeMaxDynamicSharedMemorySize, GSMEM);
    cudaFuncSetAttribute(mma_gemm<1>, cudaFuncAttributeMaxDynamicSharedMemorySize, GSMEM);

    // both weight panels in one launch
    conv_w<<<2*CONVW_BLOCKS, 256>>>(Wv, Wo);

    // proj + fused x->panel conversion
    proj_kernel<<<BL/PT, 256>>>(x, Wck, bck, Wcq, bcq, Wc, bc, pos_key);

    // value = x @ Wv^T + bv  (written as fp16 into g_valh)
    mma_gemm<0><<<dim3(DD/256, BL/128), 256, GSMEM>>>(bv, nullptr, nullptr);

    // chunked causal scan (64 chunks of 32 tokens)
    {
        dim3 grid(DD/256, NCH, BB);
        scan_partial<<<grid, 128>>>();
        scan_prefix<<<(BB*KK*DD)/256, 256>>>();
        scan_apply<<<grid, 128>>>();
    }

    // LayerNorm + fused fp16 conversion into A panel
    layernorm_conv<<<BL, 256>>>(ln_g, ln_b);

    // out = x + normed @ Wo^T + bo
    mma_gemm<1><<<dim3(DD/256, BL/128), 256, GSMEM>>>(bo, x, out);
}